// round 1
// baseline (speedup 1.0000x reference)
#include <cuda_runtime.h>
#include <math_constants.h>

#define F_DIM   128
#define RBF_N   32
#define TILE    32
#define CUTOFF_F 4.0f

// shared memory layout (in floats)
#define SH_H     0                    // [32][384]
#define SH_ACT   12288                // [32][128]
#define SH_EPI   16384                // [32][32]
#define SH_RHAT  17408                // [32][3]
#define SH_ENV   17504                // [32]
#define SH_DIST  17536                // [32]
#define SH_MU    17568                // [32]
#define SH_RSTD  17600                // [32]
#define SH_AIDX  17632                // [32] int
#define SH_PIDX  17664                // [32] int
#define SH_FLOATS 17696
#define SMEM_BYTES (SH_FLOATS * 4)

__device__ __forceinline__ float silu_f(float a) {
    return a / (1.0f + __expf(-a));
}

__global__ void __launch_bounds__(128, 3) init_out_kernel(float* rho, const float* fb, int n) {
    int i = blockIdx.x * blockDim.x + threadIdx.x;
    if (i < n) rho[i] = fb[0];
}

__global__ void __launch_bounds__(128, 3) cfr_kernel(
    const float* __restrict__ diff,
    const float* __restrict__ S,
    const float* __restrict__ V,
    const int*   __restrict__ atom_idx,
    const int*   __restrict__ probe_idx,
    const float* __restrict__ w_s1, const float* __restrict__ b_s1,
    const float* __restrict__ g_ln, const float* __restrict__ b_ln,
    const float* __restrict__ w_s2, const float* __restrict__ b_s2,
    const float* __restrict__ w_f1, const float* __restrict__ b_f1,
    const float* __restrict__ w_f2, const float* __restrict__ b_f2,
    const float* __restrict__ w_o1, const float* __restrict__ b_o1,
    const float* __restrict__ w_o2, const float* __restrict__ b_o2,
    float* __restrict__ rho,
    int E)
{
    extern __shared__ float sm[];
    float* sh_h    = sm + SH_H;
    float* sh_act  = sm + SH_ACT;
    float* sh_epi  = sm + SH_EPI;
    float* sh_rhat = sm + SH_RHAT;
    float* sh_env  = sm + SH_ENV;
    float* sh_dist = sm + SH_DIST;
    float* sh_mu   = sm + SH_MU;
    float* sh_rstd = sm + SH_RSTD;
    int*   sh_aidx = (int*)(sm + SH_AIDX);
    int*   sh_pidx = (int*)(sm + SH_PIDX);
    float* sh_g    = sm + SH_H;   // overlay: [32][64], h no longer needed by then

    const int tid = threadIdx.x;
    const int e0  = blockIdx.x * TILE;

    // ---- Phase A: per-edge scalars (32 threads, one edge each) ----
    if (tid < TILE) {
        int e = e0 + tid;
        float dx = 0.f, dy = 0.f, dz = 0.f;
        int ai = 0, pi = 0;
        if (e < E) {
            dx = diff[3 * e + 0];
            dy = diff[3 * e + 1];
            dz = diff[3 * e + 2];
            ai = atom_idx[e];
            pi = probe_idx[e];
        }
        float sq    = dx * dx + dy * dy + dz * dz;
        float dist  = sqrtf(sq);
        float dsafe = sqrtf(sq + 1e-8f);
        float inv   = 1.0f / dsafe;
        sh_rhat[tid * 3 + 0] = dx * inv;
        sh_rhat[tid * 3 + 1] = dy * inv;
        sh_rhat[tid * 3 + 2] = dz * inv;
        sh_dist[tid] = dist;
        // envelope: 1 - 21 x^5 + 35 x^6 - 15 x^7
        float x  = dist * (1.0f / CUTOFF_F);
        float x2 = x * x;
        float x5 = x2 * x2 * x;
        float env = 1.0f - 21.0f * x5 + 35.0f * x5 * x - 15.0f * x5 * x2;
        env = (e < E && dist < CUTOFF_F) ? env : 0.0f;
        sh_env[tid]  = env;
        sh_aidx[tid] = ai;
        sh_pidx[tid] = pi;
    }
    __syncthreads();

    // ---- RBF expansion: sin(n*pi*d/cutoff)/d, n=1..32 ----
    for (int i = tid; i < TILE * RBF_N; i += 128) {
        int e = i >> 5;
        int n = i & 31;
        float d = sh_dist[e];
        sh_epi[e * RBF_N + n] = sinf(d * (float)(n + 1) * (CUDART_PI_F / CUTOFF_F)) / d;
    }

    // ---- Gather atom features -> h = [S_e | n_e | q_pi], [32][384] ----
    #pragma unroll 8
    for (int e = 0; e < TILE; e++) {
        int a = sh_aidx[e];
        float s  = S[a * F_DIM + tid];
        const float* vb = V + (size_t)a * 3 * F_DIM + tid;
        float v0 = vb[0];
        float v1 = vb[F_DIM];
        float v2 = vb[2 * F_DIM];
        float rx = sh_rhat[e * 3 + 0];
        float ry = sh_rhat[e * 3 + 1];
        float rz = sh_rhat[e * 3 + 2];
        sh_h[e * 384 + tid]           = s;
        sh_h[e * 384 + 128 + tid]     = sqrtf(v0 * v0 + v1 * v1 + v2 * v2 + 1e-8f);
        sh_h[e * 384 + 256 + tid]     = v0 * rx + v1 * ry + v2 * rz;
    }
    __syncthreads();

    // ---- GEMM1: u[e] = b_s1 + h[e] @ w_s1   (K=384) ----
    float u[TILE];
    {
        float bs = b_s1[tid];
        #pragma unroll
        for (int e = 0; e < TILE; e++) u[e] = bs;
    }
    {
        const float4* h4 = (const float4*)sh_h;
        for (int k4 = 0; k4 < 96; k4++) {
            int k = k4 * 4;
            float w0 = w_s1[(k + 0) * F_DIM + tid];
            float w1 = w_s1[(k + 1) * F_DIM + tid];
            float w2 = w_s1[(k + 2) * F_DIM + tid];
            float w3 = w_s1[(k + 3) * F_DIM + tid];
            #pragma unroll
            for (int e = 0; e < TILE; e++) {
                float4 hv = h4[e * 96 + k4];
                u[e] += hv.x * w0 + hv.y * w1 + hv.z * w2 + hv.w * w3;
            }
        }
    }

    // ---- LayerNorm stats (transpose via smem, warp reduce) ----
    #pragma unroll
    for (int e = 0; e < TILE; e++) sh_act[e * F_DIM + tid] = u[e];
    __syncthreads();
    {
        int w = tid >> 5, lane = tid & 31;
        for (int j = 0; j < 8; j++) {
            int e = w * 8 + j;
            float x0 = sh_act[e * F_DIM + lane];
            float x1 = sh_act[e * F_DIM + lane + 32];
            float x2 = sh_act[e * F_DIM + lane + 64];
            float x3 = sh_act[e * F_DIM + lane + 96];
            float s = x0 + x1 + x2 + x3;
            float q = x0 * x0 + x1 * x1 + x2 * x2 + x3 * x3;
            #pragma unroll
            for (int o = 16; o > 0; o >>= 1) {
                s += __shfl_xor_sync(0xFFFFFFFFu, s, o);
                q += __shfl_xor_sync(0xFFFFFFFFu, q, o);
            }
            if (lane == 0) {
                float mu  = s * (1.0f / F_DIM);
                float var = q * (1.0f / F_DIM) - mu * mu;
                sh_mu[e]   = mu;
                sh_rstd[e] = rsqrtf(var + 1e-5f);
            }
        }
    }
    __syncthreads();

    // ---- LN affine + SiLU -> sh_act ----
    {
        float gf = g_ln[tid], bf = b_ln[tid];
        #pragma unroll
        for (int e = 0; e < TILE; e++) {
            float a = (u[e] - sh_mu[e]) * sh_rstd[e] * gf + bf;
            sh_act[e * F_DIM + tid] = silu_f(a);
        }
    }
    __syncthreads();

    // ---- GEMM2: state[e] = b_s2 + act[e] @ w_s2   (K=128) ----
    float st[TILE];
    {
        float bs = b_s2[tid];
        #pragma unroll
        for (int e = 0; e < TILE; e++) st[e] = bs;
        const float4* a4 = (const float4*)sh_act;
        for (int k4 = 0; k4 < 32; k4++) {
            int k = k4 * 4;
            float w0 = w_s2[(k + 0) * F_DIM + tid];
            float w1 = w_s2[(k + 1) * F_DIM + tid];
            float w2 = w_s2[(k + 2) * F_DIM + tid];
            float w3 = w_s2[(k + 3) * F_DIM + tid];
            #pragma unroll
            for (int e = 0; e < TILE; e++) {
                float4 av = a4[e * 32 + k4];
                st[e] += av.x * w0 + av.y * w1 + av.z * w2 + av.w * w3;
            }
        }
    }

    // ---- Filter layer 1: t[e] = silu(b_f1 + epi[e] @ w_f1)  (K=32) ----
    float t[TILE];
    {
        float bs = b_f1[tid];
        #pragma unroll
        for (int e = 0; e < TILE; e++) t[e] = bs;
        const float4* p4 = (const float4*)sh_epi;
        for (int k4 = 0; k4 < 8; k4++) {
            int k = k4 * 4;
            float w0 = w_f1[(k + 0) * F_DIM + tid];
            float w1 = w_f1[(k + 1) * F_DIM + tid];
            float w2 = w_f1[(k + 2) * F_DIM + tid];
            float w3 = w_f1[(k + 3) * F_DIM + tid];
            #pragma unroll
            for (int e = 0; e < TILE; e++) {
                float4 pv = p4[e * 8 + k4];
                t[e] += pv.x * w0 + pv.y * w1 + pv.z * w2 + pv.w * w3;
            }
        }
    }
    __syncthreads();   // everyone done reading sh_act (GEMM2)
    #pragma unroll
    for (int e = 0; e < TILE; e++) sh_act[e * F_DIM + tid] = silu_f(t[e]);
    __syncthreads();

    // ---- Filter layer 2: Wv[e] = b_f2 + act2[e] @ w_f2  (K=128) ----
    float Wv[TILE];
    {
        float bs = b_f2[tid];
        #pragma unroll
        for (int e = 0; e < TILE; e++) Wv[e] = bs;
        const float4* a4 = (const float4*)sh_act;
        for (int k4 = 0; k4 < 32; k4++) {
            int k = k4 * 4;
            float w0 = w_f2[(k + 0) * F_DIM + tid];
            float w1 = w_f2[(k + 1) * F_DIM + tid];
            float w2 = w_f2[(k + 2) * F_DIM + tid];
            float w3 = w_f2[(k + 3) * F_DIM + tid];
            #pragma unroll
            for (int e = 0; e < TILE; e++) {
                float4 av = a4[e * 32 + k4];
                Wv[e] += av.x * w0 + av.y * w1 + av.z * w2 + av.w * w3;
            }
        }
    }
    __syncthreads();   // done reading sh_act

    // ---- Fuse: z = W * state -> sh_act ----
    #pragma unroll
    for (int e = 0; e < TILE; e++) sh_act[e * F_DIM + tid] = Wv[e] * st[e];
    __syncthreads();

    // ---- Output head 1: g[e][fo] = silu(b_o1 + z[e] @ w_o1)  (K=128, N=64) ----
    {
        int fo    = tid & 63;
        int ebase = (tid >> 6) * 16;   // half the threads take edges 0-15, half 16-31
        float g[16];
        float bs = b_o1[fo];
        #pragma unroll
        for (int j = 0; j < 16; j++) g[j] = bs;
        const float4* a4 = (const float4*)sh_act;
        for (int k4 = 0; k4 < 32; k4++) {
            int k = k4 * 4;
            float w0 = w_o1[(k + 0) * 64 + fo];
            float w1 = w_o1[(k + 1) * 64 + fo];
            float w2 = w_o1[(k + 2) * 64 + fo];
            float w3 = w_o1[(k + 3) * 64 + fo];
            #pragma unroll
            for (int j = 0; j < 16; j++) {
                float4 zv = a4[(ebase + j) * 32 + k4];
                g[j] += zv.x * w0 + zv.y * w1 + zv.z * w2 + zv.w * w3;
            }
        }
        #pragma unroll
        for (int j = 0; j < 16; j++)
            sh_g[(ebase + j) * 64 + fo] = silu_f(g[j]);
    }
    __syncthreads();

    // ---- Output head 2 + envelope + scatter ----
    {
        int w = tid >> 5, lane = tid & 31;
        float wo2a = w_o2[lane];
        float wo2b = w_o2[lane + 32];
        float bo2  = b_o2[0];
        for (int j = 0; j < 8; j++) {
            int e = w * 8 + j;
            float s = sh_g[e * 64 + lane] * wo2a + sh_g[e * 64 + 32 + lane] * wo2b;
            #pragma unroll
            for (int o = 16; o > 0; o >>= 1)
                s += __shfl_xor_sync(0xFFFFFFFFu, s, o);
            if (lane == 0) {
                int ge = e0 + e;
                if (ge < E) {
                    float m = (s + bo2) * sh_env[e];
                    atomicAdd(&rho[sh_pidx[e]], m);
                }
            }
        }
    }
}

extern "C" void kernel_launch(void* const* d_in, const int* in_sizes, int n_in,
                              void* d_out, int out_size)
{
    const float* diff = (const float*)d_in[0];
    const float* S    = (const float*)d_in[1];
    const float* V    = (const float*)d_in[2];
    const int*   aidx = (const int*)d_in[3];
    const int*   pidx = (const int*)d_in[4];

    // num_probes may be present as a size-1 int input at slot 5
    int base = 5;
    if (n_in > 5 && in_sizes[5] == 1) base = 6;

    const float* w_s1 = (const float*)d_in[base + 0];
    const float* b_s1 = (const float*)d_in[base + 1];
    const float* g_ln = (const float*)d_in[base + 2];
    const float* b_ln = (const float*)d_in[base + 3];
    const float* w_s2 = (const float*)d_in[base + 4];
    const float* b_s2 = (const float*)d_in[base + 5];
    const float* w_f1 = (const float*)d_in[base + 6];
    const float* b_f1 = (const float*)d_in[base + 7];
    const float* w_f2 = (const float*)d_in[base + 8];
    const float* b_f2 = (const float*)d_in[base + 9];
    const float* w_o1 = (const float*)d_in[base + 10];
    const float* b_o1 = (const float*)d_in[base + 11];
    const float* w_o2 = (const float*)d_in[base + 12];
    const float* b_o2 = (const float*)d_in[base + 13];
    const float* fb   = (const float*)d_in[base + 14];

    int E = in_sizes[0] / 3;
    float* rho = (float*)d_out;

    init_out_kernel<<<(out_size + 127) / 128, 128>>>(rho, fb, out_size);

    cudaFuncSetAttribute(cfr_kernel, cudaFuncAttributeMaxDynamicSharedMemorySize, SMEM_BYTES);
    int tiles = (E + TILE - 1) / TILE;
    cfr_kernel<<<tiles, 128, SMEM_BYTES>>>(
        diff, S, V, aidx, pidx,
        w_s1, b_s1, g_ln, b_ln, w_s2, b_s2,
        w_f1, b_f1, w_f2, b_f2,
        w_o1, b_o1, w_o2, b_o2,
        rho, E);
}

// round 2
// speedup vs baseline: 3.8149x; 3.8149x over previous
#include <cuda_runtime.h>
#include <cuda_bf16.h>
#include <math_constants.h>

#define MTILE 64

// ---- packed bf16 weights in mma B-fragment lane order ----
// group g=(kt,nt), lane l holds 4 bf16 {w[k0][n], w[k0+1][n], w[k0+8][n], w[k0+9][n]}
// with k0 = kt*16+(l%4)*2, n = nt*8+l/4. One uint2 per (g,lane).
__device__ __align__(16) __nv_bfloat16 g_ws1p[24*16*32*4];
__device__ __align__(16) __nv_bfloat16 g_ws2p[ 8*16*32*4];
__device__ __align__(16) __nv_bfloat16 g_wf1p[ 2*16*32*4];
__device__ __align__(16) __nv_bfloat16 g_wf2p[ 8*16*32*4];
__device__ __align__(16) __nv_bfloat16 g_wo1p[ 8* 8*32*4];

__device__ __forceinline__ float silu_f(float a){ return a/(1.0f+__expf(-a)); }

__global__ void pack_weights_kernel(const float* __restrict__ ws1, const float* __restrict__ ws2,
                                    const float* __restrict__ wf1, const float* __restrict__ wf2,
                                    const float* __restrict__ wo1)
{
    int idx = blockIdx.x*blockDim.x + threadIdx.x;
    if (idx >= 736*32) return;
    int g = idx >> 5, lane = idx & 31;
    const float* src; __nv_bfloat16* dst; int NT, N, gl;
    if      (g < 384) { src=ws1; dst=g_ws1p; NT=16; N=128; gl=g;     }
    else if (g < 512) { src=ws2; dst=g_ws2p; NT=16; N=128; gl=g-384; }
    else if (g < 544) { src=wf1; dst=g_wf1p; NT=16; N=128; gl=g-512; }
    else if (g < 672) { src=wf2; dst=g_wf2p; NT=16; N=128; gl=g-544; }
    else              { src=wo1; dst=g_wo1p; NT=8;  N=64;  gl=g-672; }
    int kt = gl / NT, nt = gl % NT;
    int k0 = kt*16 + (lane&3)*2;
    int n  = nt*8 + (lane>>2);
    __nv_bfloat16* o = dst + ((size_t)gl*32 + lane)*4;
    o[0] = __float2bfloat16(src[(k0+0)*N + n]);
    o[1] = __float2bfloat16(src[(k0+1)*N + n]);
    o[2] = __float2bfloat16(src[(k0+8)*N + n]);
    o[3] = __float2bfloat16(src[(k0+9)*N + n]);
}

__global__ void init_out_kernel(float* __restrict__ rho, const float* __restrict__ fb, int n){
    int i = blockIdx.x*blockDim.x + threadIdx.x;
    if (i < n) rho[i] = fb[0];
}

// acc[NT][4] += A(16xKT*16 from smem, per-warp row base baked into a_row_addr) * B(packed)
template<int KT, int NT>
__device__ __forceinline__ void gemm_tile(float (*acc)[4], unsigned a_row_addr,
                                          const __nv_bfloat16* Bp, int lane)
{
    const uint2* Bv = reinterpret_cast<const uint2*>(Bp);
    #pragma unroll
    for (int kt = 0; kt < KT; kt++){
        unsigned a0,a1,a2,a3;
        asm volatile("ldmatrix.sync.aligned.m8n8.x4.shared.b16 {%0,%1,%2,%3}, [%4];"
            : "=r"(a0),"=r"(a1),"=r"(a2),"=r"(a3)
            : "r"(a_row_addr + kt*32));
        #pragma unroll
        for (int nt = 0; nt < NT; nt++){
            uint2 b = __ldg(&Bv[(kt*NT+nt)*32 + lane]);
            asm volatile("mma.sync.aligned.m16n8k16.row.col.f32.bf16.bf16.f32 "
                "{%0,%1,%2,%3}, {%4,%5,%6,%7}, {%8,%9}, {%0,%1,%2,%3};"
                : "+f"(acc[nt][0]),"+f"(acc[nt][1]),"+f"(acc[nt][2]),"+f"(acc[nt][3])
                : "r"(a0),"r"(a1),"r"(a2),"r"(a3), "r"(b.x), "r"(b.y));
        }
    }
}

// smem layout (bytes):
//  bufA  [64][136] bf16 @ 0      (17408)
//  bufB  [64][136] bf16 @ 17408  (17408)
//  bufE  [64][40]  bf16 @ 34816  (5120)
//  bufW  [64][136] bf16 @ 39936  (17408)
//  dist[64] f32 @57344, env[64] @57600, rhat[64][3] @57856, pidx @58624, aidx @58880
#define SMEM_BYTES 59136

__global__ void __launch_bounds__(128) cfr_mma_kernel(
    const float* __restrict__ diff, const float* __restrict__ S, const float* __restrict__ V,
    const int* __restrict__ aidx, const int* __restrict__ pidx,
    const float* __restrict__ b_s1, const float* __restrict__ g_ln, const float* __restrict__ b_ln,
    const float* __restrict__ b_s2, const float* __restrict__ b_f1, const float* __restrict__ b_f2,
    const float* __restrict__ b_o1, const float* __restrict__ w_o2, const float* __restrict__ b_o2,
    float* __restrict__ rho, int E)
{
    extern __shared__ char sm[];
    __nv_bfloat16* bufA = (__nv_bfloat16*)(sm + 0);
    __nv_bfloat16* bufB = (__nv_bfloat16*)(sm + 17408);
    __nv_bfloat16* bufE = (__nv_bfloat16*)(sm + 34816);
    __nv_bfloat16* bufW = (__nv_bfloat16*)(sm + 39936);
    float* sh_dist = (float*)(sm + 57344);
    float* sh_env  = (float*)(sm + 57600);
    float* sh_rhat = (float*)(sm + 57856);
    int*   sh_pidx = (int*)  (sm + 58624);
    int*   sh_aidx = (int*)  (sm + 58880);

    const int tid  = threadIdx.x;
    const int lane = tid & 31;
    const int warp = tid >> 5;
    const int w16  = warp * 16;
    const int e0   = blockIdx.x * MTILE + w16;

    // ---- per-edge scalars (lanes 0-15, one edge each) ----
    if (lane < 16) {
        int e = e0 + lane;
        float dx = 0.f, dy = 0.f, dz = 1e-3f;
        int ai = 0, pi = 0;
        if (e < E) { dx = diff[3*e]; dy = diff[3*e+1]; dz = diff[3*e+2]; ai = aidx[e]; pi = pidx[e]; }
        float sq   = dx*dx + dy*dy + dz*dz;
        float dist = sqrtf(sq);
        float inv  = rsqrtf(sq + 1e-8f);
        int j = w16 + lane;
        sh_rhat[j*3+0] = dx*inv;
        sh_rhat[j*3+1] = dy*inv;
        sh_rhat[j*3+2] = dz*inv;
        sh_dist[j] = dist;
        float x  = dist * 0.25f;
        float x2 = x*x, x5 = x2*x2*x;
        float env = 1.0f - 21.0f*x5 + 35.0f*x5*x - 15.0f*x5*x2;
        sh_env[j]  = (dist < 4.0f) ? env : 0.0f;
        sh_pidx[j] = pi;
        sh_aidx[j] = ai;
    }
    __syncwarp();

    // ---- sinc RBF: lane = n index (1..32), 16 edges ----
    {
        const float c  = CUDART_PI_F * 0.25f;
        const float nn = (float)(lane + 1);
        #pragma unroll
        for (int j = 0; j < 16; j++){
            float d = sh_dist[w16 + j];
            bufE[(w16+j)*40 + lane] = __float2bfloat16(__sinf(d * nn * c) / d);
        }
    }
    __syncwarp();

    const unsigned uBase = (unsigned)__cvta_generic_to_shared(sm);
    const unsigned uA = uBase + 0     + (w16 + (lane&15))*272 + ((lane>>4)<<4);
    const unsigned uB = uBase + 17408 + (w16 + (lane&15))*272 + ((lane>>4)<<4);
    const unsigned uE = uBase + 34816 + (w16 + (lane&15))*80  + ((lane>>4)<<4);

    const int q2  = (lane & 3) * 2;          // col pair offset within n-tile
    const int rlo = w16 + (lane >> 2);       // low C-fragment row (edge)
    const int rhi = rlo + 8;

    float acc[16][4];

    // ================= filter branch =================
    #pragma unroll
    for (int i = 0; i < 16; i++){ acc[i][0]=acc[i][1]=acc[i][2]=acc[i][3]=0.f; }
    gemm_tile<2,16>(acc, uE, g_wf1p, lane);                       // e_pi @ w_f1
    #pragma unroll
    for (int nt = 0; nt < 16; nt++){
        int c0 = nt*8 + q2;
        float2 bb = *(const float2*)(b_f1 + c0);
        *(__nv_bfloat162*)(bufA + rlo*136 + c0) =
            __floats2bfloat162_rn(silu_f(acc[nt][0]+bb.x), silu_f(acc[nt][1]+bb.y));
        *(__nv_bfloat162*)(bufA + rhi*136 + c0) =
            __floats2bfloat162_rn(silu_f(acc[nt][2]+bb.x), silu_f(acc[nt][3]+bb.y));
    }
    __syncwarp();

    #pragma unroll
    for (int i = 0; i < 16; i++){ acc[i][0]=acc[i][1]=acc[i][2]=acc[i][3]=0.f; }
    gemm_tile<8,16>(acc, uA, g_wf2p, lane);                       // silu(.) @ w_f2
    #pragma unroll
    for (int nt = 0; nt < 16; nt++){
        int c0 = nt*8 + q2;
        float2 bb = *(const float2*)(b_f2 + c0);
        *(__nv_bfloat162*)(bufW + rlo*136 + c0) =
            __floats2bfloat162_rn(acc[nt][0]+bb.x, acc[nt][1]+bb.y);
        *(__nv_bfloat162*)(bufW + rhi*136 + c0) =
            __floats2bfloat162_rn(acc[nt][2]+bb.x, acc[nt][3]+bb.y);
    }
    __syncwarp();

    // ================= state branch =================
    // gather S -> bufB
    for (int j = 0; j < 16; j++){
        int a = sh_aidx[w16 + j];
        const float* Sp = S + (size_t)a * 128;
        #pragma unroll
        for (int f = lane; f < 128; f += 32)
            bufB[(w16+j)*136 + f] = __float2bfloat16(Sp[f]);
    }
    __syncwarp();
    #pragma unroll
    for (int i = 0; i < 16; i++){ acc[i][0]=acc[i][1]=acc[i][2]=acc[i][3]=0.f; }
    gemm_tile<8,16>(acc, uB, g_ws1p, lane);                       // S block (k 0-127)

    // gather V -> n_e in bufA, q_pi in bufB
    for (int j = 0; j < 16; j++){
        int a = sh_aidx[w16 + j];
        float rx = sh_rhat[(w16+j)*3+0];
        float ry = sh_rhat[(w16+j)*3+1];
        float rz = sh_rhat[(w16+j)*3+2];
        const float* Vp = V + (size_t)a * 384;
        #pragma unroll
        for (int f = lane; f < 128; f += 32){
            float v0 = Vp[f], v1 = Vp[128+f], v2 = Vp[256+f];
            bufA[(w16+j)*136 + f] = __float2bfloat16(sqrtf(v0*v0+v1*v1+v2*v2+1e-8f));
            bufB[(w16+j)*136 + f] = __float2bfloat16(v0*rx + v1*ry + v2*rz);
        }
    }
    __syncwarp();
    gemm_tile<8,16>(acc, uA, g_ws1p + 16384, lane);               // n_e block (k 128-255)
    gemm_tile<8,16>(acc, uB, g_ws1p + 32768, lane);               // q_pi block (k 256-383)

    // ---- LayerNorm + SiLU (in fragments) ----
    float slo=0.f, qlo=0.f, shi=0.f, qhi=0.f;
    #pragma unroll
    for (int nt = 0; nt < 16; nt++){
        int c0 = nt*8 + q2;
        float2 bb = *(const float2*)(b_s1 + c0);
        acc[nt][0]+=bb.x; acc[nt][1]+=bb.y; acc[nt][2]+=bb.x; acc[nt][3]+=bb.y;
        slo += acc[nt][0]+acc[nt][1];  qlo += acc[nt][0]*acc[nt][0]+acc[nt][1]*acc[nt][1];
        shi += acc[nt][2]+acc[nt][3];  qhi += acc[nt][2]*acc[nt][2]+acc[nt][3]*acc[nt][3];
    }
    #pragma unroll
    for (int o = 1; o < 4; o <<= 1){
        slo += __shfl_xor_sync(0xffffffffu, slo, o);
        qlo += __shfl_xor_sync(0xffffffffu, qlo, o);
        shi += __shfl_xor_sync(0xffffffffu, shi, o);
        qhi += __shfl_xor_sync(0xffffffffu, qhi, o);
    }
    float mulo = slo*(1.f/128.f), muhi = shi*(1.f/128.f);
    float rslo = rsqrtf(qlo*(1.f/128.f) - mulo*mulo + 1e-5f);
    float rshi = rsqrtf(qhi*(1.f/128.f) - muhi*muhi + 1e-5f);
    #pragma unroll
    for (int nt = 0; nt < 16; nt++){
        int c0 = nt*8 + q2;
        float2 gg = *(const float2*)(g_ln + c0);
        float2 bl = *(const float2*)(b_ln + c0);
        float v0 = silu_f((acc[nt][0]-mulo)*rslo*gg.x + bl.x);
        float v1 = silu_f((acc[nt][1]-mulo)*rslo*gg.y + bl.y);
        float v2 = silu_f((acc[nt][2]-muhi)*rshi*gg.x + bl.x);
        float v3 = silu_f((acc[nt][3]-muhi)*rshi*gg.y + bl.y);
        *(__nv_bfloat162*)(bufA + rlo*136 + c0) = __floats2bfloat162_rn(v0, v1);
        *(__nv_bfloat162*)(bufA + rhi*136 + c0) = __floats2bfloat162_rn(v2, v3);
    }
    __syncwarp();

    // ---- state L2 + fuse z = W * state -> bufB ----
    #pragma unroll
    for (int i = 0; i < 16; i++){ acc[i][0]=acc[i][1]=acc[i][2]=acc[i][3]=0.f; }
    gemm_tile<8,16>(acc, uA, g_ws2p, lane);
    #pragma unroll
    for (int nt = 0; nt < 16; nt++){
        int c0 = nt*8 + q2;
        float2 bb  = *(const float2*)(b_s2 + c0);
        float2 wlo = __bfloat1622float2(*(__nv_bfloat162*)(bufW + rlo*136 + c0));
        float2 whi = __bfloat1622float2(*(__nv_bfloat162*)(bufW + rhi*136 + c0));
        *(__nv_bfloat162*)(bufB + rlo*136 + c0) =
            __floats2bfloat162_rn((acc[nt][0]+bb.x)*wlo.x, (acc[nt][1]+bb.y)*wlo.y);
        *(__nv_bfloat162*)(bufB + rhi*136 + c0) =
            __floats2bfloat162_rn((acc[nt][2]+bb.x)*whi.x, (acc[nt][3]+bb.y)*whi.y);
    }
    __syncwarp();

    // ---- output head: z @ w_o1 (N=64), silu, dot w_o2 ----
    #pragma unroll
    for (int i = 0; i < 8; i++){ acc[i][0]=acc[i][1]=acc[i][2]=acc[i][3]=0.f; }
    gemm_tile<8,8>(acc, uB, g_wo1p, lane);
    float mlo = 0.f, mhi = 0.f;
    #pragma unroll
    for (int nt = 0; nt < 8; nt++){
        int c0 = nt*8 + q2;
        float2 bb = *(const float2*)(b_o1 + c0);
        float2 w2 = *(const float2*)(w_o2 + c0);
        mlo += silu_f(acc[nt][0]+bb.x)*w2.x + silu_f(acc[nt][1]+bb.y)*w2.y;
        mhi += silu_f(acc[nt][2]+bb.x)*w2.x + silu_f(acc[nt][3]+bb.y)*w2.y;
    }
    mlo += __shfl_xor_sync(0xffffffffu, mlo, 1);
    mlo += __shfl_xor_sync(0xffffffffu, mlo, 2);
    mhi += __shfl_xor_sync(0xffffffffu, mhi, 1);
    mhi += __shfl_xor_sync(0xffffffffu, mhi, 2);
    if ((lane & 3) == 0){
        int r   = lane >> 2;
        float b2 = b_o2[0];
        int elo = e0 + r, ehi = elo + 8;
        if (elo < E) atomicAdd(rho + sh_pidx[w16+r],   (mlo + b2) * sh_env[w16+r]);
        if (ehi < E) atomicAdd(rho + sh_pidx[w16+r+8], (mhi + b2) * sh_env[w16+r+8]);
    }
}

extern "C" void kernel_launch(void* const* d_in, const int* in_sizes, int n_in,
                              void* d_out, int out_size)
{
    const float* diff = (const float*)d_in[0];
    const float* S    = (const float*)d_in[1];
    const float* V    = (const float*)d_in[2];
    const int*   aidx = (const int*)d_in[3];
    const int*   pidx = (const int*)d_in[4];

    int base = 5;
    if (n_in > 5 && in_sizes[5] == 1) base = 6;

    const float* w_s1 = (const float*)d_in[base + 0];
    const float* b_s1 = (const float*)d_in[base + 1];
    const float* g_ln = (const float*)d_in[base + 2];
    const float* b_ln = (const float*)d_in[base + 3];
    const float* w_s2 = (const float*)d_in[base + 4];
    const float* b_s2 = (const float*)d_in[base + 5];
    const float* w_f1 = (const float*)d_in[base + 6];
    const float* b_f1 = (const float*)d_in[base + 7];
    const float* w_f2 = (const float*)d_in[base + 8];
    const float* b_f2 = (const float*)d_in[base + 9];
    const float* w_o1 = (const float*)d_in[base + 10];
    const float* b_o1 = (const float*)d_in[base + 11];
    const float* w_o2 = (const float*)d_in[base + 12];
    const float* b_o2 = (const float*)d_in[base + 13];
    const float* fb   = (const float*)d_in[base + 14];

    int E = in_sizes[0] / 3;
    float* rho = (float*)d_out;

    pack_weights_kernel<<<(736*32 + 255)/256, 256>>>(w_s1, w_s2, w_f1, w_f2, w_o1);
    init_out_kernel<<<(out_size + 255)/256, 256>>>(rho, fb, out_size);

    cudaFuncSetAttribute(cfr_mma_kernel, cudaFuncAttributeMaxDynamicSharedMemorySize, SMEM_BYTES);
    cfr_mma_kernel<<<(E + MTILE - 1)/MTILE, 128, SMEM_BYTES>>>(
        diff, S, V, aidx, pidx,
        b_s1, g_ln, b_ln, b_s2, b_f1, b_f2,
        b_o1, w_o2, b_o2, rho, E);
}

// round 4
// speedup vs baseline: 6.2547x; 1.6396x over previous
#include <cuda_runtime.h>
#include <cuda_bf16.h>
#include <math_constants.h>

#define MTILE 64

// ---- packed bf16 weights in mma B-fragment lane order ----
// group g=(kt,nt), lane l holds 4 bf16 {w[k0][n], w[k0+1][n], w[k0+8][n], w[k0+9][n]}
// with k0 = kt*16+(l%4)*2, n = nt*8+l/4. One uint2 per (g,lane).
__device__ __align__(16) __nv_bfloat16 g_ws1p[24*16*32*4];
__device__ __align__(16) __nv_bfloat16 g_ws2p[ 8*16*32*4];
__device__ __align__(16) __nv_bfloat16 g_wf1p[ 2*16*32*4];
__device__ __align__(16) __nv_bfloat16 g_wf2p[ 8*16*32*4];
__device__ __align__(16) __nv_bfloat16 g_wo1p[ 8* 8*32*4];

__device__ __forceinline__ float silu_f(float a){ return a/(1.0f+__expf(-a)); }

__device__ __forceinline__ unsigned bf162_u32(__nv_bfloat162 v){
    return *reinterpret_cast<unsigned*>(&v);
}

// merged prep: pack weights + init rho (keeps launches/replay at 2 so ncu -s 5
// lands on the main kernel)
__global__ void prep_kernel(const float* __restrict__ ws1, const float* __restrict__ ws2,
                            const float* __restrict__ wf1, const float* __restrict__ wf2,
                            const float* __restrict__ wo1,
                            float* __restrict__ rho, const float* __restrict__ fb, int n_rho)
{
    int idx = blockIdx.x*blockDim.x + threadIdx.x;
    if (idx < 736*32) {
        int g = idx >> 5, lane = idx & 31;
        const float* src; __nv_bfloat16* dst; int NT, N, gl;
        if      (g < 384) { src=ws1; dst=g_ws1p; NT=16; N=128; gl=g;     }
        else if (g < 512) { src=ws2; dst=g_ws2p; NT=16; N=128; gl=g-384; }
        else if (g < 544) { src=wf1; dst=g_wf1p; NT=16; N=128; gl=g-512; }
        else if (g < 672) { src=wf2; dst=g_wf2p; NT=16; N=128; gl=g-544; }
        else              { src=wo1; dst=g_wo1p; NT=8;  N=64;  gl=g-672; }
        int kt = gl / NT, nt = gl % NT;
        int k0 = kt*16 + (lane&3)*2;
        int n  = nt*8 + (lane>>2);
        __nv_bfloat16* o = dst + ((size_t)gl*32 + lane)*4;
        o[0] = __float2bfloat16(src[(k0+0)*N + n]);
        o[1] = __float2bfloat16(src[(k0+1)*N + n]);
        o[2] = __float2bfloat16(src[(k0+8)*N + n]);
        o[3] = __float2bfloat16(src[(k0+9)*N + n]);
    }
    int r = idx - 736*32;
    if (r >= 0 && r < n_rho) rho[r] = fb[0];
}

// acc[NT][4] += A(16 x KT*16 from smem, per-warp row base baked in) * B(packed)
template<int KT, int NT>
__device__ __forceinline__ void gemm_tile(float (*acc)[4], unsigned a_row_addr,
                                          const __nv_bfloat16* Bp, int lane)
{
    const uint2* Bv = reinterpret_cast<const uint2*>(Bp);
    #pragma unroll
    for (int kt = 0; kt < KT; kt++){
        unsigned a0,a1,a2,a3;
        asm volatile("ldmatrix.sync.aligned.m8n8.x4.shared.b16 {%0,%1,%2,%3}, [%4];"
            : "=r"(a0),"=r"(a1),"=r"(a2),"=r"(a3)
            : "r"(a_row_addr + kt*32));
        #pragma unroll
        for (int nt = 0; nt < NT; nt++){
            uint2 b = __ldg(&Bv[(kt*NT+nt)*32 + lane]);
            asm volatile("mma.sync.aligned.m16n8k16.row.col.f32.bf16.bf16.f32 "
                "{%0,%1,%2,%3}, {%4,%5,%6,%7}, {%8,%9}, {%0,%1,%2,%3};"
                : "+f"(acc[nt][0]),"+f"(acc[nt][1]),"+f"(acc[nt][2]),"+f"(acc[nt][3])
                : "r"(a0),"r"(a1),"r"(a2),"r"(a3), "r"(b.x), "r"(b.y));
        }
    }
}

// smem layout (bytes):
//  bufA [64][136] bf16 @ 0      (17408)
//  bufB [64][136] bf16 @ 17408  (17408)
//  bufW [64][136] bf16 @ 34816  (17408)   (RBF e_pi overlays cols 0..31 early)
//  scalars @ 52224: dist(256) env(256) rhat(768) pidx(256) aidx(256)
#define OFF_A 0
#define OFF_B 17408
#define OFF_W 34816
#define OFF_SC 52224
#define SMEM_BYTES 54016

__global__ void __launch_bounds__(128, 4) cfr_mma_kernel(
    const float* __restrict__ diff, const float* __restrict__ S, const float* __restrict__ V,
    const int* __restrict__ aidx, const int* __restrict__ pidx,
    const float* __restrict__ b_s1, const float* __restrict__ g_ln, const float* __restrict__ b_ln,
    const float* __restrict__ b_s2, const float* __restrict__ b_f1, const float* __restrict__ b_f2,
    const float* __restrict__ b_o1, const float* __restrict__ w_o2, const float* __restrict__ b_o2,
    float* __restrict__ rho, int E)
{
    extern __shared__ char sm[];
    __nv_bfloat16* bufA = (__nv_bfloat16*)(sm + OFF_A);
    __nv_bfloat16* bufB = (__nv_bfloat16*)(sm + OFF_B);
    __nv_bfloat16* bufW = (__nv_bfloat16*)(sm + OFF_W);
    float* sh_dist = (float*)(sm + OFF_SC);
    float* sh_env  = (float*)(sm + OFF_SC + 256);
    float* sh_rhat = (float*)(sm + OFF_SC + 512);
    int*   sh_pidx = (int*)  (sm + OFF_SC + 1280);
    int*   sh_aidx = (int*)  (sm + OFF_SC + 1536);

    const int tid  = threadIdx.x;
    const int lane = tid & 31;
    const int warp = tid >> 5;
    const int w16  = warp * 16;
    const int e0   = blockIdx.x * MTILE + w16;

    // ---- per-edge scalars (lanes 0-15, one edge each) ----
    if (lane < 16) {
        int e = e0 + lane;
        float dx = 0.f, dy = 0.f, dz = 1e-3f;
        int ai = 0, pi = 0;
        if (e < E) { dx = diff[3*e]; dy = diff[3*e+1]; dz = diff[3*e+2]; ai = aidx[e]; pi = pidx[e]; }
        float sq   = dx*dx + dy*dy + dz*dz;
        float dist = sqrtf(sq);
        float inv  = rsqrtf(sq + 1e-8f);
        int j = w16 + lane;
        sh_rhat[j*3+0] = dx*inv;
        sh_rhat[j*3+1] = dy*inv;
        sh_rhat[j*3+2] = dz*inv;
        sh_dist[j] = dist;
        float x  = dist * 0.25f;
        float x2 = x*x, x5 = x2*x2*x;
        float env = 1.0f - 21.0f*x5 + 35.0f*x5*x - 15.0f*x5*x2;
        sh_env[j]  = (dist < 4.0f) ? env : 0.0f;
        sh_pidx[j] = pi;
        sh_aidx[j] = ai;
    }
    __syncwarp();

    // ---- sinc RBF -> bufW cols 0..31 (dead once filter GEMM1 consumes it) ----
    {
        const float c  = CUDART_PI_F * 0.25f;
        const float nn = (float)(lane + 1);
        #pragma unroll
        for (int j = 0; j < 16; j++){
            float d = sh_dist[w16 + j];
            bufW[(w16+j)*136 + lane] = __float2bfloat16(__sinf(d * nn * c) / d);
        }
    }
    __syncwarp();

    const unsigned uBase = (unsigned)__cvta_generic_to_shared(sm);
    const unsigned uRow  = (w16 + (lane&15))*272 + ((lane>>4)<<4);
    const unsigned uA = uBase + OFF_A + uRow;
    const unsigned uB = uBase + OFF_B + uRow;
    const unsigned uW = uBase + OFF_W + uRow;

    const int q2  = (lane & 3) * 2;          // col pair offset within n-tile
    const int rlo = w16 + (lane >> 2);       // low C-fragment row (edge)
    const int rhi = rlo + 8;

    float acc[16][4];

    // ================= filter branch =================
    #pragma unroll
    for (int i = 0; i < 16; i++){ acc[i][0]=acc[i][1]=acc[i][2]=acc[i][3]=0.f; }
    gemm_tile<2,16>(acc, uW, g_wf1p, lane);                       // e_pi @ w_f1
    #pragma unroll
    for (int nt = 0; nt < 16; nt++){
        int c0 = nt*8 + q2;
        float2 bb = *(const float2*)(b_f1 + c0);
        *(__nv_bfloat162*)(bufA + rlo*136 + c0) =
            __floats2bfloat162_rn(silu_f(acc[nt][0]+bb.x), silu_f(acc[nt][1]+bb.y));
        *(__nv_bfloat162*)(bufA + rhi*136 + c0) =
            __floats2bfloat162_rn(silu_f(acc[nt][2]+bb.x), silu_f(acc[nt][3]+bb.y));
    }
    __syncwarp();

    #pragma unroll
    for (int i = 0; i < 16; i++){ acc[i][0]=acc[i][1]=acc[i][2]=acc[i][3]=0.f; }
    gemm_tile<8,16>(acc, uA, g_wf2p, lane);                       // silu(.) @ w_f2
    #pragma unroll
    for (int nt = 0; nt < 16; nt++){
        int c0 = nt*8 + q2;
        float2 bb = *(const float2*)(b_f2 + c0);
        *(__nv_bfloat162*)(bufW + rlo*136 + c0) =
            __floats2bfloat162_rn(acc[nt][0]+bb.x, acc[nt][1]+bb.y);
        *(__nv_bfloat162*)(bufW + rhi*136 + c0) =
            __floats2bfloat162_rn(acc[nt][2]+bb.x, acc[nt][3]+bb.y);
    }
    __syncwarp();

    // ================= state branch =================
    // gather S -> bufB (float4 loads: 1 LDG.128 per lane per edge)
    #pragma unroll 4
    for (int j = 0; j < 16; j++){
        int a = sh_aidx[w16 + j];
        float4 s4 = __ldg((const float4*)(S + (size_t)a * 128) + lane);
        uint2 v;
        v.x = bf162_u32(__floats2bfloat162_rn(s4.x, s4.y));
        v.y = bf162_u32(__floats2bfloat162_rn(s4.z, s4.w));
        *(uint2*)(bufB + (w16+j)*136 + lane*4) = v;
    }
    __syncwarp();
    #pragma unroll
    for (int i = 0; i < 16; i++){ acc[i][0]=acc[i][1]=acc[i][2]=acc[i][3]=0.f; }
    gemm_tile<8,16>(acc, uB, g_ws1p, lane);                       // S block (k 0-127)

    // gather V (3x LDG.128/lane/edge) -> n_e in bufB, q_pi in bufA
    #pragma unroll 2
    for (int j = 0; j < 16; j++){
        int a = sh_aidx[w16 + j];
        float rx = sh_rhat[(w16+j)*3+0];
        float ry = sh_rhat[(w16+j)*3+1];
        float rz = sh_rhat[(w16+j)*3+2];
        const float4* Vp = (const float4*)(V + (size_t)a * 384);
        float4 v0 = __ldg(Vp + lane);
        float4 v1 = __ldg(Vp + 32 + lane);
        float4 v2 = __ldg(Vp + 64 + lane);
        float n0 = sqrtf(v0.x*v0.x + v1.x*v1.x + v2.x*v2.x + 1e-8f);
        float n1 = sqrtf(v0.y*v0.y + v1.y*v1.y + v2.y*v2.y + 1e-8f);
        float n2 = sqrtf(v0.z*v0.z + v1.z*v1.z + v2.z*v2.z + 1e-8f);
        float n3 = sqrtf(v0.w*v0.w + v1.w*v1.w + v2.w*v2.w + 1e-8f);
        float q0 = v0.x*rx + v1.x*ry + v2.x*rz;
        float q1 = v0.y*rx + v1.y*ry + v2.y*rz;
        float q2v= v0.z*rx + v1.z*ry + v2.z*rz;
        float q3 = v0.w*rx + v1.w*ry + v2.w*rz;
        uint2 nv, qv;
        nv.x = bf162_u32(__floats2bfloat162_rn(n0, n1));
        nv.y = bf162_u32(__floats2bfloat162_rn(n2, n3));
        qv.x = bf162_u32(__floats2bfloat162_rn(q0, q1));
        qv.y = bf162_u32(__floats2bfloat162_rn(q2v, q3));
        *(uint2*)(bufB + (w16+j)*136 + lane*4) = nv;
        *(uint2*)(bufA + (w16+j)*136 + lane*4) = qv;
    }
    __syncwarp();
    gemm_tile<8,16>(acc, uB, g_ws1p + 16384, lane);               // n_e block (k 128-255)
    gemm_tile<8,16>(acc, uA, g_ws1p + 32768, lane);               // q_pi block (k 256-383)

    // ---- LayerNorm + SiLU (in fragments) ----
    float slo=0.f, qlo=0.f, shi=0.f, qhi=0.f;
    #pragma unroll
    for (int nt = 0; nt < 16; nt++){
        int c0 = nt*8 + q2;
        float2 bb = *(const float2*)(b_s1 + c0);
        acc[nt][0]+=bb.x; acc[nt][1]+=bb.y; acc[nt][2]+=bb.x; acc[nt][3]+=bb.y;
        slo += acc[nt][0]+acc[nt][1];  qlo += acc[nt][0]*acc[nt][0]+acc[nt][1]*acc[nt][1];
        shi += acc[nt][2]+acc[nt][3];  qhi += acc[nt][2]*acc[nt][2]+acc[nt][3]*acc[nt][3];
    }
    #pragma unroll
    for (int o = 1; o < 4; o <<= 1){
        slo += __shfl_xor_sync(0xffffffffu, slo, o);
        qlo += __shfl_xor_sync(0xffffffffu, qlo, o);
        shi += __shfl_xor_sync(0xffffffffu, shi, o);
        qhi += __shfl_xor_sync(0xffffffffu, qhi, o);
    }
    float mulo = slo*(1.f/128.f), muhi = shi*(1.f/128.f);
    float rslo = rsqrtf(qlo*(1.f/128.f) - mulo*mulo + 1e-5f);
    float rshi = rsqrtf(qhi*(1.f/128.f) - muhi*muhi + 1e-5f);
    #pragma unroll
    for (int nt = 0; nt < 16; nt++){
        int c0 = nt*8 + q2;
        float2 gg = *(const float2*)(g_ln + c0);
        float2 bl = *(const float2*)(b_ln + c0);
        float v0 = silu_f((acc[nt][0]-mulo)*rslo*gg.x + bl.x);
        float v1 = silu_f((acc[nt][1]-mulo)*rslo*gg.y + bl.y);
        float v2 = silu_f((acc[nt][2]-muhi)*rshi*gg.x + bl.x);
        float v3 = silu_f((acc[nt][3]-muhi)*rshi*gg.y + bl.y);
        *(__nv_bfloat162*)(bufA + rlo*136 + c0) = __floats2bfloat162_rn(v0, v1);
        *(__nv_bfloat162*)(bufA + rhi*136 + c0) = __floats2bfloat162_rn(v2, v3);
    }
    __syncwarp();

    // ---- state L2 + fuse z = W * state -> bufB ----
    #pragma unroll
    for (int i = 0; i < 16; i++){ acc[i][0]=acc[i][1]=acc[i][2]=acc[i][3]=0.f; }
    gemm_tile<8,16>(acc, uA, g_ws2p, lane);
    #pragma unroll
    for (int nt = 0; nt < 16; nt++){
        int c0 = nt*8 + q2;
        float2 bb  = *(const float2*)(b_s2 + c0);
        float2 wlo = __bfloat1622float2(*(__nv_bfloat162*)(bufW + rlo*136 + c0));
        float2 whi = __bfloat1622float2(*(__nv_bfloat162*)(bufW + rhi*136 + c0));
        *(__nv_bfloat162*)(bufB + rlo*136 + c0) =
            __floats2bfloat162_rn((acc[nt][0]+bb.x)*wlo.x, (acc[nt][1]+bb.y)*wlo.y);
        *(__nv_bfloat162*)(bufB + rhi*136 + c0) =
            __floats2bfloat162_rn((acc[nt][2]+bb.x)*whi.x, (acc[nt][3]+bb.y)*whi.y);
    }
    __syncwarp();

    // ---- output head: z @ w_o1 (N=64), silu, dot w_o2 ----
    #pragma unroll
    for (int i = 0; i < 8; i++){ acc[i][0]=acc[i][1]=acc[i][2]=acc[i][3]=0.f; }
    gemm_tile<8,8>(acc, uB, g_wo1p, lane);
    float mlo = 0.f, mhi = 0.f;
    #pragma unroll
    for (int nt = 0; nt < 8; nt++){
        int c0 = nt*8 + q2;
        float2 bb = *(const float2*)(b_o1 + c0);
        float2 w2 = *(const float2*)(w_o2 + c0);
        mlo += silu_f(acc[nt][0]+bb.x)*w2.x + silu_f(acc[nt][1]+bb.y)*w2.y;
        mhi += silu_f(acc[nt][2]+bb.x)*w2.x + silu_f(acc[nt][3]+bb.y)*w2.y;
    }
    mlo += __shfl_xor_sync(0xffffffffu, mlo, 1);
    mlo += __shfl_xor_sync(0xffffffffu, mlo, 2);
    mhi += __shfl_xor_sync(0xffffffffu, mhi, 1);
    mhi += __shfl_xor_sync(0xffffffffu, mhi, 2);
    if ((lane & 3) == 0){
        int r   = lane >> 2;
        float b2 = b_o2[0];
        int elo = e0 + r, ehi = elo + 8;
        if (elo < E) atomicAdd(rho + sh_pidx[w16+r],   (mlo + b2) * sh_env[w16+r]);
        if (ehi < E) atomicAdd(rho + sh_pidx[w16+r+8], (mhi + b2) * sh_env[w16+r+8]);
    }
}

extern "C" void kernel_launch(void* const* d_in, const int* in_sizes, int n_in,
                              void* d_out, int out_size)
{
    const float* diff = (const float*)d_in[0];
    const float* S    = (const float*)d_in[1];
    const float* V    = (const float*)d_in[2];
    const int*   aidx = (const int*)d_in[3];
    const int*   pidx = (const int*)d_in[4];

    int base = 5;
    if (n_in > 5 && in_sizes[5] == 1) base = 6;

    const float* w_s1 = (const float*)d_in[base + 0];
    const float* b_s1 = (const float*)d_in[base + 1];
    const float* g_ln = (const float*)d_in[base + 2];
    const float* b_ln = (const float*)d_in[base + 3];
    const float* w_s2 = (const float*)d_in[base + 4];
    const float* b_s2 = (const float*)d_in[base + 5];
    const float* w_f1 = (const float*)d_in[base + 6];
    const float* b_f1 = (const float*)d_in[base + 7];
    const float* w_f2 = (const float*)d_in[base + 8];
    const float* b_f2 = (const float*)d_in[base + 9];
    const float* w_o1 = (const float*)d_in[base + 10];
    const float* b_o1 = (const float*)d_in[base + 11];
    const float* w_o2 = (const float*)d_in[base + 12];
    const float* b_o2 = (const float*)d_in[base + 13];
    const float* fb   = (const float*)d_in[base + 14];

    int E = in_sizes[0] / 3;
    float* rho = (float*)d_out;

    int prep_threads = 736*32 + out_size;
    prep_kernel<<<(prep_threads + 255)/256, 256>>>(w_s1, w_s2, w_f1, w_f2, w_o1,
                                                   rho, fb, out_size);

    cudaFuncSetAttribute(cfr_mma_kernel, cudaFuncAttributeMaxDynamicSharedMemorySize, SMEM_BYTES);
    cfr_mma_kernel<<<(E + MTILE - 1)/MTILE, 128, SMEM_BYTES>>>(
        diff, S, V, aidx, pidx,
        b_s1, g_ln, b_ln, b_s2, b_f1, b_f2,
        b_o1, w_o2, b_o2, rho, E);
}